// round 11
// baseline (speedup 1.0000x reference)
#include <cuda_runtime.h>
#include <cuda_bf16.h>

// Problem constants (must match reference)
#define NUM_NODES   1200000
#define NUM_PHYS    1000000
#define NUM_MOVABLE 900000
#define NB          512
#define NT          (NB / 2)      // 256 tiles per axis
#define KSTEN       5

// BSX = BSY = 1000/512 = 1.953125 (exact in fp32)
#define BS 1.953125f

// Compile-time double folds, cast to f32 exactly as JAX weak-type promotion does
__device__ __forceinline__ float stretch_c() { return (float)(1.953125 * 1.4142135623730951); }
__device__ __forceinline__ float cap_denom() { return (float)(1.953125 * 1.953125 * 0.05); }
__device__ __forceinline__ float min_rate()  { return (float)(1.0 / 1.5); }

// Scratch (no allocations allowed). Bin maps stored in a 2x2-TILED layout:
//   lin(ix, iy) = ((ix>>1)*NT + (iy>>1))*4 + (ix&1)*2 + (iy&1)
// so one 16B-aligned float4 covers the 2x2 bin patch {ix0,ix0+1}x{iy0,iy0+1}.
// k_util is elementwise and layout-agnostic. __device__ globals are zero-init
// at load; k_util re-zeroes g_pin_map every run, so "pin_map == 0 at scatter
// entry" holds for the correctness call, capture call, and every replay.
__device__ __align__(16) float g_pin_map[NB * NB];
__device__ __align__(16) float g_util[NB * NB];

// One-instruction 2x2 reduction: adds a float4 to a 16B-aligned address.
__device__ __forceinline__ void red_add_v4(float* addr, float a, float b, float c, float d) {
    asm volatile("red.global.add.v4.f32 [%0], {%1, %2, %3, %4};"
                 :: "l"(addr), "f"(a), "f"(b), "f"(c), "f"(d) : "memory");
}

// ---------------------------------------------------------------------------
// Packed overlap stencil. Matches reference _overlap_terms exactly:
//   il = clip(floor(lo/BS), 0, NB-1); idx = il+k; valid = idx < NB;
//   idx = min(idx, NB-1); b_lo = idx*BS;
//   ov = max(min(hi,b_lo+BS) - max(lo,b_lo), 0); zero where invalid.
// Extents here are < 2.05 bins, so only taps k=0..2 can be nonzero (taps 3,4
// are identically zero in the reference too). The 3 taps are placed into a
// 2-aligned 4-slot window starting at bin (il & ~1); unused slots stay 0.
// True division lo/BS so floor matches JAX bit-for-bit at bin boundaries.
// Returns the tile index (il>>1); need1 = second tile has a nonzero slot.
// ---------------------------------------------------------------------------
__device__ __forceinline__ int overlap3_packed(float lo, float hi, float scale,
                                               float v[4], bool& need1) {
    int il = (int)floorf(lo / BS);
    il = min(max(il, 0), NB - 1);
    int s = il & 1;
    v[0] = v[1] = v[2] = v[3] = 0.0f;
#pragma unroll
    for (int k = 0; k < 3; k++) {
        int id = il + k;
        bool valid = id < NB;
        id = min(id, NB - 1);
        float b_lo = (float)id * BS;              // exact: id*125/64 fits in 24 bits
        float o = fmaxf(fminf(hi, b_lo + BS) - fmaxf(lo, b_lo), 0.0f);
        v[s + k] = valid ? o * scale : 0.0f;      // s+k <= 3
    }
    need1 = (v[2] != 0.0f) || (v[3] != 0.0f);
    return il >> 1;
}

// ---------------------------------------------------------------------------
// Kernel 1: scatter pin density into the tiled bin map.
// Per node: <=2 x-tiles x <=2 y-tiles, each committed with ONE v4 RED holding
// the 2x2 outer-product patch. ~3.0 RED instructions/node vs ~4.3 RED.64
// before. Zero-pad products add exact +-0.0: bit-exact no-ops.
// ---------------------------------------------------------------------------
__global__ void __launch_bounds__(256) k_scatter(const float* __restrict__ pos,
                                                 const float* __restrict__ nsx,
                                                 const float* __restrict__ nsy,
                                                 const int*   __restrict__ pin_start) {
    int i = blockIdx.x * blockDim.x + threadIdx.x;
    if (i >= NUM_PHYS) return;

    float sx = nsx[i];
    float sy = nsy[i];
    float hx = 0.5f * fmaxf(stretch_c(), sx);
    float hy = 0.5f * fmaxf(stretch_c(), sy);
    float cx = pos[i]             + 0.5f * sx;
    float cy = pos[NUM_NODES + i] + 0.5f * sy;

    float pw = (float)(pin_start[i + 1] - pin_start[i]);
    float density = pw / (4.0f * hx * hy);

    float xv[4], yv[4];
    bool xn1, yn1;
    int tx0 = overlap3_packed(cx - hx, cx + hx, 1.0f,    xv, xn1);
    int ty0 = overlap3_packed(cy - hy, cy + hy, density, yv, yn1);

#pragma unroll
    for (int xt = 0; xt < 2; xt++) {
        if (xt == 1 && !xn1) break;
        float rx0 = xv[2 * xt], rx1 = xv[2 * xt + 1];
        float* colbase = &g_pin_map[((tx0 + xt) * NT + ty0) * 4];
#pragma unroll
        for (int yt = 0; yt < 2; yt++) {
            if (yt == 1 && !yn1) break;
            float y0 = yv[2 * yt], y1 = yv[2 * yt + 1];
            red_add_v4(colbase + yt * 4,
                       rx0 * y0, rx0 * y1, rx1 * y0, rx1 * y1);
        }
    }
}

// ---------------------------------------------------------------------------
// Kernel 2: util = clip(pin_map / (BSX*BSY*cap), 1/1.5, 1.5)   (elementwise:
// layout permutation is transparent) + re-zero pin_map for the next replay.
// ---------------------------------------------------------------------------
__global__ void __launch_bounds__(256) k_util() {
    int i = blockIdx.x * blockDim.x + threadIdx.x;
    if (i >= NB * NB) return;
    float u = g_pin_map[i] / cap_denom();
    g_util[i] = fminf(fmaxf(u, min_rate()), 1.5f);
    g_pin_map[i] = 0.0f;
}

// ---------------------------------------------------------------------------
// Kernel 3: per-movable-node weighted gather from the tiled util map.
// <=4 LDG.128 per node (one per 2x2 tile) instead of ~4.3 LDG.64.
// ---------------------------------------------------------------------------
__global__ void __launch_bounds__(256) k_gather(const float* __restrict__ pos,
                                                const float* __restrict__ nsx,
                                                const float* __restrict__ nsy,
                                                float* __restrict__ out) {
    int m = blockIdx.x * blockDim.x + threadIdx.x;
    if (m >= NUM_MOVABLE) return;

    float x_lo = pos[m];
    float x_hi = x_lo + nsx[m];
    float y_lo = pos[NUM_NODES + m];
    float y_hi = y_lo + nsy[m];

    float xw[4], yw[4];
    bool xn1, yn1;
    int tx0 = overlap3_packed(x_lo, x_hi, 1.0f, xw, xn1);
    int ty0 = overlap3_packed(y_lo, y_hi, 1.0f, yw, yn1);

    float acc = 0.0f;
#pragma unroll
    for (int xt = 0; xt < 2; xt++) {
        if (xt == 1 && !xn1) break;
        float wx0 = xw[2 * xt], wx1 = xw[2 * xt + 1];
        const float* colbase = &g_util[((tx0 + xt) * NT + ty0) * 4];
#pragma unroll
        for (int yt = 0; yt < 2; yt++) {
            if (yt == 1 && !yn1) break;
            float w0 = yw[2 * yt], w1 = yw[2 * yt + 1];
            float4 u = *(const float4*)(colbase + yt * 4);   // LDG.128, 16B-aligned
            acc += wx0 * (w0 * u.x + w1 * u.y)
                 + wx1 * (w0 * u.z + w1 * u.w);
        }
    }
    out[m] = acc;
}

// ---------------------------------------------------------------------------
extern "C" void kernel_launch(void* const* d_in, const int* in_sizes, int n_in,
                              void* d_out, int out_size) {
    const float* pos       = (const float*)d_in[0];   // 2*NUM_NODES
    const float* nsx       = (const float*)d_in[1];   // NUM_NODES
    const float* nsy       = (const float*)d_in[2];   // NUM_NODES
    const int*   pin_start = (const int*)  d_in[3];   // NUM_PHYS+1
    float*       out       = (float*)d_out;           // NUM_MOVABLE

    k_scatter<<<(NUM_PHYS + 255) / 256, 256>>>(pos, nsx, nsy, pin_start);
    k_util<<<(NB * NB + 255) / 256, 256>>>();
    k_gather<<<(NUM_MOVABLE + 255) / 256, 256>>>(pos, nsx, nsy, out);
}

// round 12
// speedup vs baseline: 1.2425x; 1.2425x over previous
#include <cuda_runtime.h>
#include <cuda_bf16.h>

// Problem constants (must match reference)
#define NUM_NODES   1200000
#define NUM_PHYS    1000000
#define NUM_MOVABLE 900000
#define NB          512
#define KSTEN       5

// BSX = BSY = 1000/512 = 1.953125 (exact in fp32)
#define BS 1.953125f

// Compile-time double folds, cast to f32 exactly as JAX weak-type promotion does
__device__ __forceinline__ float stretch_c() { return (float)(1.953125 * 1.4142135623730951); }
__device__ __forceinline__ float cap_denom() { return (float)(1.953125 * 1.953125 * 0.05); }
__device__ __forceinline__ float min_rate()  { return (float)(1.0 / 1.5); }

// Scratch (no allocations allowed). Row-major bin maps, 16B-aligned so that
// pair windows at (a & 3) == 0 admit float4 RED/LDG. __device__ globals are
// zero-init at load; k_util re-zeroes g_pin_map every run, so "pin_map == 0
// at scatter entry" holds for correctness call, capture call, every replay.
__device__ __align__(16) float g_pin_map[NB * NB];
__device__ __align__(16) float g_util[NB * NB];

__device__ __forceinline__ void red_add_v2(float* addr, float x, float y) {
    asm volatile("red.global.add.v2.f32 [%0], {%1, %2};"
                 :: "l"(addr), "f"(x), "f"(y) : "memory");
}
__device__ __forceinline__ void red_add_v4(float* addr, float a, float b, float c, float d) {
    asm volatile("red.global.add.v4.f32 [%0], {%1, %2, %3, %4};"
                 :: "l"(addr), "f"(a), "f"(b), "f"(c), "f"(d) : "memory");
}

// ---------------------------------------------------------------------------
// Overlap stencil — matches reference _overlap_terms exactly:
//   il = clip(floor(lo/BS), 0, NB-1); idx = il + k; valid = idx < NB;
//   idx = min(idx, NB-1); b_lo = idx*BS;
//   ov = max(min(hi, b_lo+BS) - max(lo, b_lo), 0); 0 where invalid.
// True division lo/BS so floor matches JAX bit-for-bit at bin boundaries.
// ---------------------------------------------------------------------------
__device__ __forceinline__ void overlap_terms(float lo, float hi,
                                              int idx[KSTEN], float ov[KSTEN]) {
    int il = (int)floorf(lo / BS);
    il = min(max(il, 0), NB - 1);
#pragma unroll
    for (int k = 0; k < KSTEN; k++) {
        int id = il + k;
        bool valid = id < NB;
        id = min(id, NB - 1);
        float b_lo = (float)id * BS;              // exact: id*125/64 fits in 24 bits
        float o = fminf(hi, b_lo + BS) - fmaxf(lo, b_lo);
        o = fmaxf(o, 0.0f);
        idx[k] = id;
        ov[k]  = valid ? o : 0.0f;
    }
}

// ---------------------------------------------------------------------------
// Kernel 1: scatter pin density into the bin map.
// Y-stencil (span always <= 3 taps: extent 1.414 bins) packed into aligned
// float2 pairs. X loops over all 5 taps (x can span 4 bins — sx up to 4.0).
// Per x-row: one v2, plus the second pair when needed; when both pairs are
// needed AND the window is 16B-aligned, fuse into a single v4 RED (same
// values, same addresses; pads add exact +0.0 -> bit-exact no-op).
// ---------------------------------------------------------------------------
__global__ void __launch_bounds__(256) k_scatter(const float* __restrict__ pos,
                                                 const float* __restrict__ nsx,
                                                 const float* __restrict__ nsy,
                                                 const int*   __restrict__ pin_start) {
    int i = blockIdx.x * blockDim.x + threadIdx.x;
    if (i >= NUM_PHYS) return;

    float sx = nsx[i];
    float sy = nsy[i];
    float hx = 0.5f * fmaxf(stretch_c(), sx);
    float hy = 0.5f * fmaxf(stretch_c(), sy);
    float cx = pos[i]             + 0.5f * sx;
    float cy = pos[NUM_NODES + i] + 0.5f * sy;

    float pw = (float)(pin_start[i + 1] - pin_start[i]);
    float density = pw / (4.0f * hx * hy);

    int   ix[KSTEN], iy[KSTEN];
    float ovx[KSTEN], ovy[KSTEN];
    overlap_terms(cx - hx, cx + hx, ix, ovx);
    overlap_terms(cy - hy, cy + hy, iy, ovy);

    // Pack y contributions (span <= 3, at iy[0]..iy[0]+2) into 4 pair-aligned
    // slots starting at a = iy[0] & ~1. ovy[3], ovy[4] are always 0 in y.
    int j0 = iy[0];
    int s  = j0 & 1;
    int a  = j0 - s;
    float v0 = 0.0f, v1 = 0.0f, v2 = 0.0f, v3 = 0.0f;
    float d0 = ovy[0] * density;
    float d1 = ovy[1] * density;
    float d2 = ovy[2] * density;
    if (s == 0) { v0 = d0; v1 = d1; v2 = d2; }
    else        { v1 = d0; v2 = d1; v3 = d2; }
    bool need_p1 = (v2 != 0.0f) || (v3 != 0.0f);
    bool fuse4   = need_p1 && ((a & 3) == 0);     // 16B-aligned window

#pragma unroll
    for (int kx = 0; kx < KSTEN; kx++) {
        float r = ovx[kx];
        if (r == 0.0f) continue;                  // skip zero x-rows
        float* rowp = &g_pin_map[ix[kx] * NB + a];
        if (fuse4) {
            red_add_v4(rowp, r * v0, r * v1, r * v2, r * v3);
        } else {
            red_add_v2(rowp, r * v0, r * v1);
            if (need_p1)
                red_add_v2(rowp + 2, r * v2, r * v3);
        }
    }
}

// ---------------------------------------------------------------------------
// Kernel 2: util = clip(pin_map / (BSX*BSY*cap), 1/1.5, 1.5)
//           + re-zero pin_map for the next graph replay
// ---------------------------------------------------------------------------
__global__ void __launch_bounds__(256) k_util() {
    int i = blockIdx.x * blockDim.x + threadIdx.x;
    if (i >= NB * NB) return;
    float u = g_pin_map[i] / cap_denom();
    g_util[i] = fminf(fmaxf(u, min_rate()), 1.5f);
    g_pin_map[i] = 0.0f;
}

// ---------------------------------------------------------------------------
// Kernel 3: per-movable-node weighted gather of util -> instance pin area.
// Y-span <= 3 (sy = 2.0 -> 1.024 bins); x loops all 5 taps (nsx up to 4.0).
// Two aligned float2 loads per x-row, fused into one float4 when the window
// is 16B-aligned. Zero-weight slots contribute exactly 0.
// ---------------------------------------------------------------------------
__global__ void __launch_bounds__(256) k_gather(const float* __restrict__ pos,
                                                const float* __restrict__ nsx,
                                                const float* __restrict__ nsy,
                                                float* __restrict__ out) {
    int m = blockIdx.x * blockDim.x + threadIdx.x;
    if (m >= NUM_MOVABLE) return;

    float x_lo = pos[m];
    float x_hi = x_lo + nsx[m];
    float y_lo = pos[NUM_NODES + m];
    float y_hi = y_lo + nsy[m];

    int   jx[KSTEN], jy[KSTEN];
    float wx[KSTEN], wy[KSTEN];
    overlap_terms(x_lo, x_hi, jx, wx);
    overlap_terms(y_lo, y_hi, jy, wy);

    int j0 = jy[0];
    int s  = j0 & 1;
    int a  = j0 - s;
    float v0 = 0.0f, v1 = 0.0f, v2 = 0.0f, v3 = 0.0f;
    if (s == 0) { v0 = wy[0]; v1 = wy[1]; v2 = wy[2]; }
    else        { v1 = wy[0]; v2 = wy[1]; v3 = wy[2]; }
    bool need_p1 = (v2 != 0.0f) || (v3 != 0.0f);
    bool fuse4   = need_p1 && ((a & 3) == 0);

    float acc = 0.0f;
#pragma unroll
    for (int kx = 0; kx < KSTEN; kx++) {
        float wxk = wx[kx];
        if (wxk == 0.0f) continue;                // whole row contributes 0
        const float* rowp = &g_util[jx[kx] * NB + a];
        if (fuse4) {
            float4 u = *(const float4*)rowp;      // LDG.128, 16B-aligned
            acc += wxk * (v0 * u.x + v1 * u.y);
            acc += wxk * (v2 * u.z + v3 * u.w);
        } else {
            float2 u0 = *(const float2*)rowp;     // LDG.64, 8B-aligned
            acc += wxk * (v0 * u0.x + v1 * u0.y);
            if (need_p1) {
                float2 u1 = *(const float2*)(rowp + 2);
                acc += wxk * (v2 * u1.x + v3 * u1.y);
            }
        }
    }
    out[m] = acc;
}

// ---------------------------------------------------------------------------
extern "C" void kernel_launch(void* const* d_in, const int* in_sizes, int n_in,
                              void* d_out, int out_size) {
    const float* pos       = (const float*)d_in[0];   // 2*NUM_NODES
    const float* nsx       = (const float*)d_in[1];   // NUM_NODES
    const float* nsy       = (const float*)d_in[2];   // NUM_NODES
    const int*   pin_start = (const int*)  d_in[3];   // NUM_PHYS+1
    float*       out       = (float*)d_out;           // NUM_MOVABLE

    k_scatter<<<(NUM_PHYS + 255) / 256, 256>>>(pos, nsx, nsy, pin_start);
    k_util<<<(NB * NB + 255) / 256, 256>>>();
    k_gather<<<(NUM_MOVABLE + 255) / 256, 256>>>(pos, nsx, nsy, out);
}

// round 13
// speedup vs baseline: 1.3051x; 1.0504x over previous
#include <cuda_runtime.h>
#include <cuda_bf16.h>

// Problem constants (must match reference)
#define NUM_NODES   1200000
#define NUM_PHYS    1000000
#define NUM_MOVABLE 900000
#define NB          512
#define KSTEN       5

// BSX = BSY = 1000/512 = 1.953125 (exact in fp32)
#define BS 1.953125f

// Compile-time double folds, cast to f32 exactly as JAX weak-type promotion does
__device__ __forceinline__ float stretch_c() { return (float)(1.953125 * 1.4142135623730951); }
__device__ __forceinline__ float cap_denom() { return (float)(1.953125 * 1.953125 * 0.05); }
__device__ __forceinline__ float min_rate()  { return (float)(1.0 / 1.5); }

// Scratch (no allocations allowed). Row-major bin maps, 16B-aligned so that
// pair windows at (a & 3) == 0 admit float4 RED and k_util can run float4.
// __device__ globals are zero-init at load; k_util re-zeroes g_pin_map every
// run, so "pin_map == 0 at scatter entry" holds for the correctness call,
// the capture call, and every graph replay.
__device__ __align__(16) float g_pin_map[NB * NB];
__device__ __align__(16) float g_util[NB * NB];

__device__ __forceinline__ void red_add_v2(float* addr, float x, float y) {
    asm volatile("red.global.add.v2.f32 [%0], {%1, %2};"
                 :: "l"(addr), "f"(x), "f"(y) : "memory");
}
__device__ __forceinline__ void red_add_v4(float* addr, float a, float b, float c, float d) {
    asm volatile("red.global.add.v4.f32 [%0], {%1, %2, %3, %4};"
                 :: "l"(addr), "f"(a), "f"(b), "f"(c), "f"(d) : "memory");
}

// ---------------------------------------------------------------------------
// Overlap stencil — matches reference _overlap_terms exactly:
//   il = clip(floor(lo/BS), 0, NB-1); idx = il + k; valid = idx < NB;
//   idx = min(idx, NB-1); b_lo = idx*BS;
//   ov = max(min(hi, b_lo+BS) - max(lo, b_lo), 0); 0 where invalid.
// True division lo/BS so floor matches JAX bit-for-bit at bin boundaries.
// ---------------------------------------------------------------------------
__device__ __forceinline__ void overlap_terms(float lo, float hi,
                                              int idx[KSTEN], float ov[KSTEN]) {
    int il = (int)floorf(lo / BS);
    il = min(max(il, 0), NB - 1);
#pragma unroll
    for (int k = 0; k < KSTEN; k++) {
        int id = il + k;
        bool valid = id < NB;
        id = min(id, NB - 1);
        float b_lo = (float)id * BS;              // exact: id*125/64 fits in 24 bits
        float o = fminf(hi, b_lo + BS) - fmaxf(lo, b_lo);
        o = fmaxf(o, 0.0f);
        idx[k] = id;
        ov[k]  = valid ? o : 0.0f;
    }
}

// ---------------------------------------------------------------------------
// Kernel 1: scatter pin density into the bin map.  (unchanged from R12 —
// measured win, do not touch.)
// Y-stencil (span <= 3 taps) packed into aligned float2 pairs; x loops all
// 5 taps (x can span 4 bins — sx up to 4.0). Per x-row: one v2, plus the
// second pair when needed; when both pairs are needed AND the window is
// 16B-aligned, fuse into a single v4 RED (pads add exact +0.0 — no-op).
// ---------------------------------------------------------------------------
__global__ void __launch_bounds__(256) k_scatter(const float* __restrict__ pos,
                                                 const float* __restrict__ nsx,
                                                 const float* __restrict__ nsy,
                                                 const int*   __restrict__ pin_start) {
    int i = blockIdx.x * blockDim.x + threadIdx.x;
    if (i >= NUM_PHYS) return;

    float sx = nsx[i];
    float sy = nsy[i];
    float hx = 0.5f * fmaxf(stretch_c(), sx);
    float hy = 0.5f * fmaxf(stretch_c(), sy);
    float cx = pos[i]             + 0.5f * sx;
    float cy = pos[NUM_NODES + i] + 0.5f * sy;

    float pw = (float)(pin_start[i + 1] - pin_start[i]);
    float density = pw / (4.0f * hx * hy);

    int   ix[KSTEN], iy[KSTEN];
    float ovx[KSTEN], ovy[KSTEN];
    overlap_terms(cx - hx, cx + hx, ix, ovx);
    overlap_terms(cy - hy, cy + hy, iy, ovy);

    // Pack y contributions (span <= 3, at iy[0]..iy[0]+2) into 4 pair-aligned
    // slots starting at a = iy[0] & ~1. ovy[3], ovy[4] are always 0 in y.
    int j0 = iy[0];
    int s  = j0 & 1;
    int a  = j0 - s;
    float v0 = 0.0f, v1 = 0.0f, v2 = 0.0f, v3 = 0.0f;
    float d0 = ovy[0] * density;
    float d1 = ovy[1] * density;
    float d2 = ovy[2] * density;
    if (s == 0) { v0 = d0; v1 = d1; v2 = d2; }
    else        { v1 = d0; v2 = d1; v3 = d2; }
    bool need_p1 = (v2 != 0.0f) || (v3 != 0.0f);
    bool fuse4   = need_p1 && ((a & 3) == 0);     // 16B-aligned window

#pragma unroll
    for (int kx = 0; kx < KSTEN; kx++) {
        float r = ovx[kx];
        if (r == 0.0f) continue;                  // skip zero x-rows
        float* rowp = &g_pin_map[ix[kx] * NB + a];
        if (fuse4) {
            red_add_v4(rowp, r * v0, r * v1, r * v2, r * v3);
        } else {
            red_add_v2(rowp, r * v0, r * v1);
            if (need_p1)
                red_add_v2(rowp + 2, r * v2, r * v3);
        }
    }
}

// ---------------------------------------------------------------------------
// Kernel 2: util = clip(pin_map / (BSX*BSY*cap), 1/1.5, 1.5), float4-wide,
//           + re-zero pin_map for the next graph replay.
// ---------------------------------------------------------------------------
__global__ void __launch_bounds__(256) k_util() {
    int i = blockIdx.x * blockDim.x + threadIdx.x;
    if (i >= (NB * NB) / 4) return;
    float4 p = ((const float4*)g_pin_map)[i];
    float4 u;
    u.x = fminf(fmaxf(p.x / cap_denom(), min_rate()), 1.5f);
    u.y = fminf(fmaxf(p.y / cap_denom(), min_rate()), 1.5f);
    u.z = fminf(fmaxf(p.z / cap_denom(), min_rate()), 1.5f);
    u.w = fminf(fmaxf(p.w / cap_denom(), min_rate()), 1.5f);
    ((float4*)g_util)[i] = u;
    ((float4*)g_pin_map)[i] = make_float4(0.0f, 0.0f, 0.0f, 0.0f);
}

// ---------------------------------------------------------------------------
// Kernel 3: per-movable-node weighted gather of util -> instance pin area.
// Branch-free pair loads (R10 form): the fuse4 if/else measured SLOWER here —
// mixed-predicate warps execute both paths for loads, unlike fire-and-forget
// REDs. Y-span <= 3 (sy = 2.0); x loops all 5 taps. Zero-weight slots
// contribute exactly 0; skipped second pair is an exact no-op.
// ---------------------------------------------------------------------------
__global__ void __launch_bounds__(256) k_gather(const float* __restrict__ pos,
                                                const float* __restrict__ nsx,
                                                const float* __restrict__ nsy,
                                                float* __restrict__ out) {
    int m = blockIdx.x * blockDim.x + threadIdx.x;
    if (m >= NUM_MOVABLE) return;

    float x_lo = pos[m];
    float x_hi = x_lo + nsx[m];
    float y_lo = pos[NUM_NODES + m];
    float y_hi = y_lo + nsy[m];

    int   jx[KSTEN], jy[KSTEN];
    float wx[KSTEN], wy[KSTEN];
    overlap_terms(x_lo, x_hi, jx, wx);
    overlap_terms(y_lo, y_hi, jy, wy);

    // Pack y weights into 4 pair-aligned slots (span <= 3 at jy[0]..jy[0]+2).
    int j0 = jy[0];
    int s  = j0 & 1;
    int a  = j0 - s;
    float v0 = 0.0f, v1 = 0.0f, v2 = 0.0f, v3 = 0.0f;
    if (s == 0) { v0 = wy[0]; v1 = wy[1]; v2 = wy[2]; }
    else        { v1 = wy[0]; v2 = wy[1]; v3 = wy[2]; }
    bool need_p1 = (v2 != 0.0f) || (v3 != 0.0f);

    float acc = 0.0f;
#pragma unroll
    for (int kx = 0; kx < KSTEN; kx++) {
        float wxk = wx[kx];
        if (wxk == 0.0f) continue;                // whole row contributes 0
        const float* rowp = &g_util[jx[kx] * NB + a];
        float2 u0 = *(const float2*)rowp;         // LDG.64, 8B-aligned
        acc += wxk * (v0 * u0.x + v1 * u0.y);
        if (need_p1) {
            float2 u1 = *(const float2*)(rowp + 2);
            acc += wxk * (v2 * u1.x + v3 * u1.y);
        }
    }
    out[m] = acc;
}

// ---------------------------------------------------------------------------
extern "C" void kernel_launch(void* const* d_in, const int* in_sizes, int n_in,
                              void* d_out, int out_size) {
    const float* pos       = (const float*)d_in[0];   // 2*NUM_NODES
    const float* nsx       = (const float*)d_in[1];   // NUM_NODES
    const float* nsy       = (const float*)d_in[2];   // NUM_NODES
    const int*   pin_start = (const int*)  d_in[3];   // NUM_PHYS+1
    float*       out       = (float*)d_out;           // NUM_MOVABLE

    k_scatter<<<(NUM_PHYS + 255) / 256, 256>>>(pos, nsx, nsy, pin_start);
    k_util<<<((NB * NB) / 4 + 255) / 256, 256>>>();
    k_gather<<<(NUM_MOVABLE + 255) / 256, 256>>>(pos, nsx, nsy, out);
}